// round 3
// baseline (speedup 1.0000x reference)
#include <cuda_runtime.h>

// Problem constants (fixed by the reference: AdaBIGGAN last adaptive stage)
#define BB 32
#define CC 96
#define HH 128
#define WW 128
#define INF 148   // hypernet input dim

#define HW (HH * WW)          // 16384 floats per (b,c) plane
#define HW4 (HW / 4)          // 4096 float4 per plane

// Scratch for per-(b,c) scale/bias (no cudaMalloc allowed)
__device__ float g_scale[BB * CC];
__device__ float g_bias [BB * CC];

// ---------------------------------------------------------------------------
// Kernel 1: hypernetwork collapse.
// scale[b,c] = y[b] . wsum_c + bsum_c,  wsum_c[i] = sum_j Wg_w[(c*C+j)*IN + i]
// bias [b,c] = y[b] . Bg_w[c]  + Bg_b[c]
// One block per channel c. 256 threads.
// ---------------------------------------------------------------------------
__global__ __launch_bounds__(256) void hyper_kernel(
    const float* __restrict__ y,      // [B, IN]
    const float* __restrict__ Wg_w,   // [C*C, IN]
    const float* __restrict__ Wg_b,   // [C*C]
    const float* __restrict__ Bg_w,   // [C, IN]
    const float* __restrict__ Bg_b)   // [C]
{
    const int c   = blockIdx.x;
    const int tid = threadIdx.x;

    __shared__ float wsum[INF];
    __shared__ float bgw [INF];
    __shared__ float red [256];
    __shared__ float bsum_s;

    // Column-wise reduction of Wg_w rows for this channel (coalesced in i).
    if (tid < INF) {
        float s = 0.f;
        const float* base = Wg_w + (size_t)c * CC * INF + tid;
        #pragma unroll 4
        for (int j = 0; j < CC; ++j) s += base[(size_t)j * INF];
        wsum[tid] = s;
        bgw[tid]  = Bg_w[c * INF + tid];
    }

    // Reduce Wg_b over the 96 rows of this channel.
    float pb = 0.f;
    for (int j = tid; j < CC; j += 256) pb += Wg_b[c * CC + j];
    red[tid] = pb;
    __syncthreads();
    #pragma unroll
    for (int s = 128; s > 0; s >>= 1) {
        if (tid < s) red[tid] += red[tid + s];
        __syncthreads();
    }
    if (tid == 0) bsum_s = red[0];
    __syncthreads();

    const float bsum = bsum_s;
    const float bgb  = Bg_b[c];

    // 8 warps; each warp handles batches b = warp, warp+8, ... (4 each).
    const int warp = tid >> 5;
    const int lane = tid & 31;
    for (int b = warp; b < BB; b += 8) {
        float ds = 0.f, db = 0.f;
        const float* yb = y + b * INF;
        for (int i = lane; i < INF; i += 32) {
            const float yv = yb[i];
            ds = fmaf(yv, wsum[i], ds);
            db = fmaf(yv, bgw[i],  db);
        }
        #pragma unroll
        for (int o = 16; o > 0; o >>= 1) {
            ds += __shfl_down_sync(0xffffffffu, ds, o);
            db += __shfl_down_sync(0xffffffffu, db, o);
        }
        if (lane == 0) {
            g_scale[b * CC + c] = ds + bsum;
            g_bias [b * CC + c] = db + bgb;
        }
    }
}

// ---------------------------------------------------------------------------
// Kernel 2: HBM-bound stream.  out = relu(h * scale[bc] + bias[bc])
// grid = (HW4/256, B*C), float4 per thread.
// ---------------------------------------------------------------------------
__global__ __launch_bounds__(256) void affine_relu_kernel(
    const float* __restrict__ h,
    float* __restrict__ out)
{
    const int bc  = blockIdx.y;
    const float s  = g_scale[bc];
    const float bi = g_bias[bc];

    const int idx = blockIdx.x * blockDim.x + threadIdx.x;  // 0..HW4-1
    const float4* __restrict__ hp = reinterpret_cast<const float4*>(h + (size_t)bc * HW);
    float4*       __restrict__ op = reinterpret_cast<float4*>(out + (size_t)bc * HW);

    float4 v = hp[idx];
    v.x = fmaxf(fmaf(v.x, s, bi), 0.f);
    v.y = fmaxf(fmaf(v.y, s, bi), 0.f);
    v.z = fmaxf(fmaf(v.z, s, bi), 0.f);
    v.w = fmaxf(fmaf(v.w, s, bi), 0.f);
    op[idx] = v;
}

// ---------------------------------------------------------------------------
// Launch. Input order per metadata: h, y, Wg_w, Wg_b, Bg_w, Bg_b
// ---------------------------------------------------------------------------
extern "C" void kernel_launch(void* const* d_in, const int* in_sizes, int n_in,
                              void* d_out, int out_size)
{
    const float* h    = (const float*)d_in[0];
    const float* y    = (const float*)d_in[1];
    const float* Wg_w = (const float*)d_in[2];
    const float* Wg_b = (const float*)d_in[3];
    const float* Bg_w = (const float*)d_in[4];
    const float* Bg_b = (const float*)d_in[5];
    float* out = (float*)d_out;

    hyper_kernel<<<CC, 256>>>(y, Wg_w, Wg_b, Bg_w, Bg_b);

    dim3 grid(HW4 / 256, BB * CC);   // (16, 3072)
    affine_relu_kernel<<<grid, 256>>>(h, out);
}

// round 5
// speedup vs baseline: 1.2048x; 1.2048x over previous
#include <cuda_runtime.h>

// Problem constants (fixed by the reference: AdaBIGGAN last adaptive stage)
#define BB 32
#define CC 96
#define HH 128
#define WW 128
#define INF 148   // hypernet input dim

#define HW  (HH * WW)         // 16384 floats per (b,c) plane
#define HW4 (HW / 4)          // 4096 float4 per plane

// Scratch for per-(b,c) scale/bias (no cudaMalloc allowed)
__device__ float g_scale[BB * CC];
__device__ float g_bias [BB * CC];

// ---------------------------------------------------------------------------
// Kernel 1: hypernetwork collapse (high-MLP version).
// scale[b,c] = y[b] . wsum_c + bsum_c,  wsum_c[i] = sum_j Wg_w[(c*C+j)*IN + i]
// bias [b,c] = y[b] . Bg_w[c]  + Bg_b[c]
// One block per channel c. 8 warps each reduce 12 of the 96 j-rows across all
// i columns -> 256 active threads, ~60 independent loads per thread.
// ---------------------------------------------------------------------------
__global__ __launch_bounds__(256) void hyper_kernel(
    const float* __restrict__ y,      // [B, IN]
    const float* __restrict__ Wg_w,   // [C*C, IN]
    const float* __restrict__ Wg_b,   // [C*C]
    const float* __restrict__ Bg_w,   // [C, IN]
    const float* __restrict__ Bg_b)   // [C]
{
    const int c    = blockIdx.x;
    const int tid  = threadIdx.x;
    const int warp = tid >> 5;
    const int lane = tid & 31;

    __shared__ float part[8][INF];    // per-warp partial column sums
    __shared__ float wsum[INF];
    __shared__ float bgw [INF];
    __shared__ float red [256];
    __shared__ float bsum_s;

    const float* base = Wg_w + (size_t)c * CC * INF;

    // Each warp sums rows j = warp, warp+8, ..., lanes stride columns i.
    for (int i = lane; i < INF; i += 32) {
        float s = 0.f;
        #pragma unroll
        for (int j = warp; j < CC; j += 8)
            s += __ldg(base + (size_t)j * INF + i);
        part[warp][i] = s;
    }

    // Reduce Wg_b over the 96 rows of this channel (independent of part[]).
    float pb = 0.f;
    for (int j = tid; j < CC; j += 256) pb += Wg_b[c * CC + j];
    red[tid] = pb;
    __syncthreads();

    // Combine warp partials into wsum; load Bg_w row.
    if (tid < INF) {
        float s = 0.f;
        #pragma unroll
        for (int w = 0; w < 8; ++w) s += part[w][tid];
        wsum[tid] = s;
        bgw[tid]  = Bg_w[c * INF + tid];
    }
    #pragma unroll
    for (int s = 128; s > 0; s >>= 1) {
        if (tid < s) red[tid] += red[tid + s];
        __syncthreads();
    }
    if (tid == 0) bsum_s = red[0];
    __syncthreads();

    const float bsum = bsum_s;
    const float bgb  = Bg_b[c];

    // 8 warps; each warp handles 4 batches via shuffle-reduced dot products.
    for (int b = warp; b < BB; b += 8) {
        float ds = 0.f, db = 0.f;
        const float* yb = y + b * INF;
        for (int i = lane; i < INF; i += 32) {
            const float yv = yb[i];
            ds = fmaf(yv, wsum[i], ds);
            db = fmaf(yv, bgw[i],  db);
        }
        #pragma unroll
        for (int o = 16; o > 0; o >>= 1) {
            ds += __shfl_down_sync(0xffffffffu, ds, o);
            db += __shfl_down_sync(0xffffffffu, db, o);
        }
        if (lane == 0) {
            g_scale[b * CC + c] = ds + bsum;
            g_bias [b * CC + c] = db + bgb;
        }
    }
}

// ---------------------------------------------------------------------------
// Kernel 2: HBM-bound stream.  out = relu(h * scale[bc] + bias[bc])
// grid = (4, B*C), 256 threads, 4 float4 per thread (front-batched -> MLP 4).
// Streaming cache hints: no reuse of h or out.
// ---------------------------------------------------------------------------
__global__ __launch_bounds__(256) void affine_relu_kernel(
    const float* __restrict__ h,
    float* __restrict__ out)
{
    const int bc   = blockIdx.y;
    const float s  = g_scale[bc];
    const float bi = g_bias[bc];

    const float4* __restrict__ hp = reinterpret_cast<const float4*>(h  + (size_t)bc * HW);
    float4*       __restrict__ op = reinterpret_cast<float4*>      (out + (size_t)bc * HW);

    const int base = blockIdx.x * 1024 + threadIdx.x;

    float4 v0 = __ldcs(hp + base);
    float4 v1 = __ldcs(hp + base + 256);
    float4 v2 = __ldcs(hp + base + 512);
    float4 v3 = __ldcs(hp + base + 768);

    v0.x = fmaxf(fmaf(v0.x, s, bi), 0.f);
    v0.y = fmaxf(fmaf(v0.y, s, bi), 0.f);
    v0.z = fmaxf(fmaf(v0.z, s, bi), 0.f);
    v0.w = fmaxf(fmaf(v0.w, s, bi), 0.f);
    v1.x = fmaxf(fmaf(v1.x, s, bi), 0.f);
    v1.y = fmaxf(fmaf(v1.y, s, bi), 0.f);
    v1.z = fmaxf(fmaf(v1.z, s, bi), 0.f);
    v1.w = fmaxf(fmaf(v1.w, s, bi), 0.f);
    v2.x = fmaxf(fmaf(v2.x, s, bi), 0.f);
    v2.y = fmaxf(fmaf(v2.y, s, bi), 0.f);
    v2.z = fmaxf(fmaf(v2.z, s, bi), 0.f);
    v2.w = fmaxf(fmaf(v2.w, s, bi), 0.f);
    v3.x = fmaxf(fmaf(v3.x, s, bi), 0.f);
    v3.y = fmaxf(fmaf(v3.y, s, bi), 0.f);
    v3.z = fmaxf(fmaf(v3.z, s, bi), 0.f);
    v3.w = fmaxf(fmaf(v3.w, s, bi), 0.f);

    __stcs(op + base,       v0);
    __stcs(op + base + 256, v1);
    __stcs(op + base + 512, v2);
    __stcs(op + base + 768, v3);
}

// ---------------------------------------------------------------------------
// Launch. Input order per metadata: h, y, Wg_w, Wg_b, Bg_w, Bg_b
// ---------------------------------------------------------------------------
extern "C" void kernel_launch(void* const* d_in, const int* in_sizes, int n_in,
                              void* d_out, int out_size)
{
    const float* h    = (const float*)d_in[0];
    const float* y    = (const float*)d_in[1];
    const float* Wg_w = (const float*)d_in[2];
    const float* Wg_b = (const float*)d_in[3];
    const float* Bg_w = (const float*)d_in[4];
    const float* Bg_b = (const float*)d_in[5];
    float* out = (float*)d_out;

    hyper_kernel<<<CC, 256>>>(y, Wg_w, Wg_b, Bg_w, Bg_b);

    dim3 grid(HW4 / 1024, BB * CC);   // (4, 3072)
    affine_relu_kernel<<<grid, 256>>>(h, out);
}

// round 9
// speedup vs baseline: 1.2579x; 1.0441x over previous
#include <cuda_runtime.h>

// Problem constants (AdaBIGGAN last adaptive stage)
#define BB 32
#define CC 96
#define HH 128
#define WW 128
#define INF 148               // hypernet input dim (= 37 float4)
#define INF4 37

#define HW  (HH * WW)         // 16384 floats per (b,c) plane
#define HW4 (HW / 4)          // 4096 float4 per plane

// Scratch for per-(b,c) scale/bias (no cudaMalloc allowed)
__device__ float g_scale[BB * CC];
__device__ float g_bias [BB * CC];

// ---------------------------------------------------------------------------
// Kernel 1: hypernetwork collapse, vectorized + high-MLP.
// scale[b,c] = y[b] . wsum_c + bsum_c,  wsum_c[i] = sum_j Wg_w[(c*C+j)*IN + i]
// bias [b,c] = y[b] . Bg_w[c]  + Bg_b[c]
// One block per channel c. Phase 1: 222 threads = 6 jgroups x 37 float4-cols;
// each thread sums 16 independent float4 rows (256B in flight per thread).
// Phase 2: combine 6 partials per column. Phase 3: shuffle-reduced dots.
// ---------------------------------------------------------------------------
__global__ __launch_bounds__(256) void hyper_kernel(
    const float* __restrict__ y,      // [B, IN]
    const float* __restrict__ Wg_w,   // [C*C, IN]
    const float* __restrict__ Wg_b,   // [C*C]
    const float* __restrict__ Bg_w,   // [C, IN]
    const float* __restrict__ Bg_b)   // [C]
{
    const int c    = blockIdx.x;
    const int tid  = threadIdx.x;
    const int warp = tid >> 5;
    const int lane = tid & 31;

    __shared__ float part[6][INF];    // per-jgroup partial column sums
    __shared__ float wsum[INF];
    __shared__ float bgw [INF];
    __shared__ float red [256];
    __shared__ float bsum_s;

    const float4* base4 = reinterpret_cast<const float4*>(Wg_w + (size_t)c * CC * INF);

    // Phase 1: threads 0..221. jgroup = t/37 (rows jg, jg+6, ... : 16 rows),
    // i4 = t%37 (float4 column). All 16 loads independent -> deep MLP.
    if (tid < 6 * INF4) {
        const int jg = tid / INF4;
        const int i4 = tid - jg * INF4;
        float4 acc = make_float4(0.f, 0.f, 0.f, 0.f);
        #pragma unroll
        for (int r = 0; r < 16; ++r) {
            const int j = jg + 6 * r;
            float4 v = __ldg(base4 + (size_t)j * INF4 + i4);
            acc.x += v.x; acc.y += v.y; acc.z += v.z; acc.w += v.w;
        }
        part[jg][i4 * 4 + 0] = acc.x;
        part[jg][i4 * 4 + 1] = acc.y;
        part[jg][i4 * 4 + 2] = acc.z;
        part[jg][i4 * 4 + 3] = acc.w;
    }

    // Wg_b reduction for this channel (independent of part[]).
    float pb = 0.f;
    for (int j = tid; j < CC; j += 256) pb += Wg_b[c * CC + j];
    red[tid] = pb;
    __syncthreads();

    // Phase 2: combine the 6 jgroup partials; load Bg_w row.
    if (tid < INF) {
        float s = part[0][tid] + part[1][tid] + part[2][tid]
                + part[3][tid] + part[4][tid] + part[5][tid];
        wsum[tid] = s;
        bgw[tid]  = Bg_w[c * INF + tid];
    }
    #pragma unroll
    for (int s = 128; s > 0; s >>= 1) {
        if (tid < s) red[tid] += red[tid + s];
        __syncthreads();
    }
    if (tid == 0) bsum_s = red[0];
    __syncthreads();

    const float bsum = bsum_s;
    const float bgb  = Bg_b[c];

    // Phase 3: 8 warps; each warp computes 4 batches' dot products.
    for (int b = warp; b < BB; b += 8) {
        float ds = 0.f, db = 0.f;
        const float* yb = y + b * INF;
        #pragma unroll
        for (int i = lane; i < INF; i += 32) {
            const float yv = yb[i];
            ds = fmaf(yv, wsum[i], ds);
            db = fmaf(yv, bgw[i],  db);
        }
        #pragma unroll
        for (int o = 16; o > 0; o >>= 1) {
            ds += __shfl_down_sync(0xffffffffu, ds, o);
            db += __shfl_down_sync(0xffffffffu, db, o);
        }
        if (lane == 0) {
            g_scale[b * CC + c] = ds + bsum;
            g_bias [b * CC + c] = db + bgb;
        }
    }
}

// ---------------------------------------------------------------------------
// Kernel 2: HBM-bound stream.  out = relu(h * scale[bc] + bias[bc])
// grid = (2, B*C), 256 threads, 8 front-batched float4 per thread (MLP_p1=8).
// Streaming cache hints: no reuse of h or out.
// ---------------------------------------------------------------------------
__global__ __launch_bounds__(256) void affine_relu_kernel(
    const float* __restrict__ h,
    float* __restrict__ out)
{
    const int bc   = blockIdx.y;
    const float s  = g_scale[bc];
    const float bi = g_bias[bc];

    const float4* __restrict__ hp = reinterpret_cast<const float4*>(h  + (size_t)bc * HW);
    float4*       __restrict__ op = reinterpret_cast<float4*>      (out + (size_t)bc * HW);

    const int base = blockIdx.x * 2048 + threadIdx.x;

    float4 v[8];
    #pragma unroll
    for (int k = 0; k < 8; ++k)
        v[k] = __ldcs(hp + base + k * 256);

    #pragma unroll
    for (int k = 0; k < 8; ++k) {
        v[k].x = fmaxf(fmaf(v[k].x, s, bi), 0.f);
        v[k].y = fmaxf(fmaf(v[k].y, s, bi), 0.f);
        v[k].z = fmaxf(fmaf(v[k].z, s, bi), 0.f);
        v[k].w = fmaxf(fmaf(v[k].w, s, bi), 0.f);
    }

    #pragma unroll
    for (int k = 0; k < 8; ++k)
        __stcs(op + base + k * 256, v[k]);
}

// ---------------------------------------------------------------------------
// Launch. Input order per metadata: h, y, Wg_w, Wg_b, Bg_w, Bg_b
// ---------------------------------------------------------------------------
extern "C" void kernel_launch(void* const* d_in, const int* in_sizes, int n_in,
                              void* d_out, int out_size)
{
    const float* h    = (const float*)d_in[0];
    const float* y    = (const float*)d_in[1];
    const float* Wg_w = (const float*)d_in[2];
    const float* Wg_b = (const float*)d_in[3];
    const float* Bg_w = (const float*)d_in[4];
    const float* Bg_b = (const float*)d_in[5];
    float* out = (float*)d_out;

    hyper_kernel<<<CC, 256>>>(y, Wg_w, Wg_b, Bg_w, Bg_b);

    dim3 grid(HW4 / 2048, BB * CC);   // (2, 3072)
    affine_relu_kernel<<<grid, 256>>>(h, out);
}

// round 10
// speedup vs baseline: 1.3081x; 1.0400x over previous
#include <cuda_runtime.h>

// Problem constants (AdaBIGGAN last adaptive stage)
#define BB 32
#define CC 96
#define HH 128
#define WW 128
#define INF 148               // hypernet input dim

#define HW  (HH * WW)         // 16384 floats per (b,c) plane
#define HW4 (HW / 4)          // 4096 float4 per plane

#define NGRP 4                // row-groups per channel in kernel 1
#define ROWS_PER_GRP (CC / NGRP)   // 24

// Scratch (no cudaMalloc allowed)
__device__ float g_part [CC * NGRP * INF];  // partial column sums of Wg_w
__device__ float g_bpart[CC * NGRP];        // partial sums of Wg_b

// ---------------------------------------------------------------------------
// Kernel 1: wide partial reduction of Wg_w / Wg_b.
// Block (c,g) sums rows j = g*24 .. g*24+23 of channel c's 96x148 slab,
// column-wise (coalesced in i). 384 blocks, 160 threads.
// ---------------------------------------------------------------------------
__global__ __launch_bounds__(160) void part_kernel(
    const float* __restrict__ Wg_w,   // [C*C, IN]
    const float* __restrict__ Wg_b)   // [C*C]
{
    const int blk = blockIdx.x;          // 0..383
    const int c   = blk >> 2;
    const int g   = blk & 3;
    const int tid = threadIdx.x;

    const float* base = Wg_w + ((size_t)c * CC + g * ROWS_PER_GRP) * INF;

    if (tid < INF) {
        float s = 0.f;
        #pragma unroll
        for (int r = 0; r < ROWS_PER_GRP; ++r)
            s += __ldg(base + (size_t)r * INF + tid);
        g_part[blk * INF + tid] = s;
    }

    // Wg_b partial for this (c,g): 24 values, warp-0 shuffle reduce.
    if (tid < 32) {
        float pb = (tid < ROWS_PER_GRP)
                 ? __ldg(Wg_b + c * CC + g * ROWS_PER_GRP + tid) : 0.f;
        #pragma unroll
        for (int o = 16; o > 0; o >>= 1)
            pb += __shfl_down_sync(0xffffffffu, pb, o);
        if (tid == 0) g_bpart[blk] = pb;
    }
}

// ---------------------------------------------------------------------------
// Kernel 2: fused dot-prologue + HBM stream.
//   scale = y[b] . (sum_g part[c][g]) + sum_g bpart[c][g]
//   bias  = y[b] . Bg_w[c] + Bg_b[c]
//   out   = relu(h * scale + bias)
// grid = (4, B*C), 256 threads, 4 front-batched float4 per thread.
// h loads are issued before the prologue, hiding the dot under DRAM latency.
// ---------------------------------------------------------------------------
__global__ __launch_bounds__(256) void affine_relu_kernel(
    const float* __restrict__ h,
    const float* __restrict__ y,      // [B, IN]
    const float* __restrict__ Bg_w,   // [C, IN]
    const float* __restrict__ Bg_b,   // [C]
    float* __restrict__ out)
{
    const int bc  = blockIdx.y;           // b*CC + c (matches [B,C,H,W] planes)
    const int c   = bc % CC;
    const int b   = bc / CC;
    const int tid = threadIdx.x;

    // ---- issue the streaming loads FIRST (independent of prologue) ----
    const float4* __restrict__ hp = reinterpret_cast<const float4*>(h  + (size_t)bc * HW);
    float4*       __restrict__ op = reinterpret_cast<float4*>      (out + (size_t)bc * HW);
    const int base = blockIdx.x * 1024 + tid;

    float4 v0 = __ldcs(hp + base);
    float4 v1 = __ldcs(hp + base + 256);
    float4 v2 = __ldcs(hp + base + 512);
    float4 v3 = __ldcs(hp + base + 768);

    // ---- prologue: per-(b,c) scale/bias dot (all operands L2-resident) ----
    __shared__ float sh_ds[8], sh_db[8];
    __shared__ float sh_s, sh_b;

    float ds = 0.f, db = 0.f;
    if (tid < INF) {
        const float yv = __ldg(y + b * INF + tid);
        const float* pp = g_part + (size_t)(c * NGRP) * INF + tid;
        const float w = pp[0] + pp[INF] + pp[2 * INF] + pp[3 * INF];
        ds = yv * w;
        db = yv * __ldg(Bg_w + c * INF + tid);
    }
    #pragma unroll
    for (int o = 16; o > 0; o >>= 1) {
        ds += __shfl_down_sync(0xffffffffu, ds, o);
        db += __shfl_down_sync(0xffffffffu, db, o);
    }
    const int warp = tid >> 5, lane = tid & 31;
    if (lane == 0) { sh_ds[warp] = ds; sh_db[warp] = db; }
    __syncthreads();
    if (tid == 0) {
        float S = sh_ds[0] + sh_ds[1] + sh_ds[2] + sh_ds[3]
                + sh_ds[4] + sh_ds[5] + sh_ds[6] + sh_ds[7];
        float D = sh_db[0] + sh_db[1] + sh_db[2] + sh_db[3]
                + sh_db[4] + sh_db[5] + sh_db[6] + sh_db[7];
        const float* bp = g_bpart + c * NGRP;
        S += bp[0] + bp[1] + bp[2] + bp[3];
        D += __ldg(Bg_b + c);
        sh_s = S; sh_b = D;
    }
    __syncthreads();
    const float s  = sh_s;
    const float bi = sh_b;

    // ---- affine + relu + streaming stores ----
    v0.x = fmaxf(fmaf(v0.x, s, bi), 0.f);
    v0.y = fmaxf(fmaf(v0.y, s, bi), 0.f);
    v0.z = fmaxf(fmaf(v0.z, s, bi), 0.f);
    v0.w = fmaxf(fmaf(v0.w, s, bi), 0.f);
    v1.x = fmaxf(fmaf(v1.x, s, bi), 0.f);
    v1.y = fmaxf(fmaf(v1.y, s, bi), 0.f);
    v1.z = fmaxf(fmaf(v1.z, s, bi), 0.f);
    v1.w = fmaxf(fmaf(v1.w, s, bi), 0.f);
    v2.x = fmaxf(fmaf(v2.x, s, bi), 0.f);
    v2.y = fmaxf(fmaf(v2.y, s, bi), 0.f);
    v2.z = fmaxf(fmaf(v2.z, s, bi), 0.f);
    v2.w = fmaxf(fmaf(v2.w, s, bi), 0.f);
    v3.x = fmaxf(fmaf(v3.x, s, bi), 0.f);
    v3.y = fmaxf(fmaf(v3.y, s, bi), 0.f);
    v3.z = fmaxf(fmaf(v3.z, s, bi), 0.f);
    v3.w = fmaxf(fmaf(v3.w, s, bi), 0.f);

    __stcs(op + base,       v0);
    __stcs(op + base + 256, v1);
    __stcs(op + base + 512, v2);
    __stcs(op + base + 768, v3);
}

// ---------------------------------------------------------------------------
// Launch. Input order per metadata: h, y, Wg_w, Wg_b, Bg_w, Bg_b
// ---------------------------------------------------------------------------
extern "C" void kernel_launch(void* const* d_in, const int* in_sizes, int n_in,
                              void* d_out, int out_size)
{
    const float* h    = (const float*)d_in[0];
    const float* y    = (const float*)d_in[1];
    const float* Wg_w = (const float*)d_in[2];
    const float* Wg_b = (const float*)d_in[3];
    const float* Bg_w = (const float*)d_in[4];
    const float* Bg_b = (const float*)d_in[5];
    float* out = (float*)d_out;

    part_kernel<<<CC * NGRP, 160>>>(Wg_w, Wg_b);

    dim3 grid(HW4 / 1024, BB * CC);   // (4, 3072)
    affine_relu_kernel<<<grid, 256>>>(h, y, Bg_w, Bg_b, out);
}